// round 9
// baseline (speedup 1.0000x reference)
#include <cuda_runtime.h>
#include <math.h>

// Problem dims
#define T_STEPS 16384
#define E_DIM   1024
#define H_DIM   1024
#define R_DIM   4096   // 4*H

// Recurrent kernel config
#define NBLK     128   // persistent blocks (<=148 SMs, 1/SM by smem)
#define JPB      8     // h-lanes per block (NBLK*JPB = H_DIM)
#define RTHREADS 256   // 8 warps, 1 warp per h-lane

// GEMM config
#define BM 64
#define BN 64
#define BK 32

// ---------------- device scratch (no allocations allowed) ----------------
__device__ float              g_xg[(size_t)T_STEPS * R_DIM];    // 256 MB input projections
__device__ unsigned long long g_hpair[2][H_DIM];                // {tag,h} fused pairs, tag-parity buffered
__device__ float              g_sumexp[(size_t)T_STEPS * NBLK]; // per-(step,block) partial sum(exp(h))
__device__ float              g_hy[T_STEPS];                    // h[y_t] per step

// ---------------- kernel 1: xg = Xs @ W_ih^T + b_ih + b_hh ----------------
__global__ void __launch_bounds__(256) xg_gemm(
    const float* __restrict__ Xs, const float* __restrict__ W_ih,
    const float* __restrict__ b_ih, const float* __restrict__ b_hh)
{
    __shared__ float As[BM][BK + 4];
    __shared__ float Bs[BN][BK + 4];

    const int bm  = blockIdx.y * BM;   // timestep tile
    const int bn  = blockIdx.x * BN;   // gate-row tile
    const int tid = threadIdx.x;
    const int tx  = tid & 15;          // 16 x 16 thread grid
    const int ty  = tid >> 4;

    float acc[4][4];
#pragma unroll
    for (int i = 0; i < 4; i++)
#pragma unroll
        for (int jj = 0; jj < 4; jj++) acc[i][jj] = 0.0f;

    for (int k0 = 0; k0 < E_DIM; k0 += BK) {
#pragma unroll
        for (int i = 0; i < 2; i++) {
            int idx = tid + i * 256;          // 0..511
            int r   = idx >> 3;               // row 0..63
            int c4  = (idx & 7) << 2;         // col 0..28 step 4
            float4 va = *(const float4*)&Xs[(size_t)(bm + r) * E_DIM + k0 + c4];
            As[r][c4 + 0] = va.x; As[r][c4 + 1] = va.y;
            As[r][c4 + 2] = va.z; As[r][c4 + 3] = va.w;
            float4 vb = *(const float4*)&W_ih[(size_t)(bn + r) * E_DIM + k0 + c4];
            Bs[r][c4 + 0] = vb.x; Bs[r][c4 + 1] = vb.y;
            Bs[r][c4 + 2] = vb.z; Bs[r][c4 + 3] = vb.w;
        }
        __syncthreads();

#pragma unroll
        for (int kk = 0; kk < BK; kk++) {
            float a[4], b[4];
#pragma unroll
            for (int i = 0; i < 4; i++)  a[i]  = As[ty * 4 + i][kk];
#pragma unroll
            for (int jj = 0; jj < 4; jj++) b[jj] = Bs[tx * 4 + jj][kk];
#pragma unroll
            for (int i = 0; i < 4; i++)
#pragma unroll
                for (int jj = 0; jj < 4; jj++)
                    acc[i][jj] += a[i] * b[jj];
        }
        __syncthreads();
    }

#pragma unroll
    for (int i = 0; i < 4; i++) {
        int t = bm + ty * 4 + i;
#pragma unroll
        for (int jj = 0; jj < 4; jj++) {
            int r = bn + tx * 4 + jj;
            g_xg[(size_t)t * R_DIM + r] = acc[i][jj] + __ldg(&b_ih[r]) + __ldg(&b_hh[r]);
        }
    }
}

// ---------------- kernel 2: persistent LSTM recurrence ----------------
// Block b owns h-lanes j = b*8 .. b*8+7 (one warp per lane).
// Sync: each h published as one atomic 8B {tag,h} via st.release.gpu.b64.
// Consumers poll the pair itself: tag current => h already in hand.
#define RNN_SMEM ((32 * 1024 + 1024 + 16) * sizeof(float))

__global__ void __launch_bounds__(RTHREADS, 1) lstm_rnn(
    const float* __restrict__ W_hh, const long long* __restrict__ ys)
{
    extern __shared__ float smem[];
    float* Wsm = smem;                 // 32 rows x 1024
    float* hsm = smem + 32 * 1024;     // 1024
    float* red = hsm + 1024;           // 2 x 8 (parity double-buffered)

    const int tid  = threadIdx.x;
    const int b    = blockIdx.x;
    const int w    = tid >> 5;
    const int lane = tid & 31;
    const int j    = b * JPB + w;

    // Load this block's 32 W_hh rows into smem (rows j, H+j, 2H+j, 3H+j per warp)
#pragma unroll
    for (int r = 0; r < 4; r++) {
        const float* src = W_hh + (size_t)(r * H_DIM + j) * H_DIM;
        float*       dst = Wsm + (size_t)(w * 4 + r) * H_DIM;
        for (int k = lane * 4; k < H_DIM; k += 128) {
            *(float4*)(dst + k) = *(const float4*)(src + k);
        }
    }

    // tag base: all pairs in buf0 are uniform at kernel entry (0 on first run,
    // base+T after each completed run). Read our own block's pair.
    __shared__ unsigned s_base;
    if (tid == 0) {
        unsigned long long v;
        asm volatile("ld.acquire.gpu.b64 %0, [%1];"
                     : "=l"(v) : "l"(&g_hpair[0][b * JPB]) : "memory");
        s_base = (unsigned)(v >> 32);
    }
    // zero hsm for t=0 (h_0 = 0)
    *(float4*)&hsm[tid * 4] = make_float4(0.f, 0.f, 0.f, 0.f);
    __syncthreads();
    const unsigned base = s_base;

    const float* w0 = Wsm + (size_t)(w * 4 + 0) * H_DIM;
    const float* w1 = Wsm + (size_t)(w * 4 + 1) * H_DIM;
    const float* w2 = Wsm + (size_t)(w * 4 + 2) * H_DIM;
    const float* w3 = Wsm + (size_t)(w * 4 + 3) * H_DIM;

    float c_state = 0.0f;

    // software-pipelined xg / ys prefetch (one full step ahead)
    const float* xgp0 = &g_xg[(size_t)0 * R_DIM + j];
    float xi = __ldg(xgp0 + 0 * H_DIM);
    float xf = __ldg(xgp0 + 1 * H_DIM);
    float xg_ = __ldg(xgp0 + 2 * H_DIM);
    float xo = __ldg(xgp0 + 3 * H_DIM);
    long long yt = __ldg(&ys[0]);

    for (int t = 0; t < T_STEPS; t++) {
        // issue next step's xg/ys loads now (consumed ~2000 cyc later)
        int tn = (t + 1 < T_STEPS) ? t + 1 : t;
        const float* xgp = &g_xg[(size_t)tn * R_DIM + j];
        float nxi = __ldg(xgp + 0 * H_DIM);
        float nxf = __ldg(xgp + 1 * H_DIM);
        float nxg = __ldg(xgp + 2 * H_DIM);
        float nxo = __ldg(xgp + 3 * H_DIM);
        long long nyt = __ldg(&ys[tn]);

        // stage h_prev: poll 4 fused {tag,h} pairs per thread
        if (t > 0) {
            const unsigned tgt = base + (unsigned)t;
            unsigned long long* src = &g_hpair[t & 1][tid * 4];
            unsigned long long v0, v1, v2, v3;
            for (;;) {
                asm volatile("ld.acquire.gpu.b64 %0, [%1];" : "=l"(v0) : "l"(src + 0) : "memory");
                asm volatile("ld.acquire.gpu.b64 %0, [%1];" : "=l"(v1) : "l"(src + 1) : "memory");
                asm volatile("ld.acquire.gpu.b64 %0, [%1];" : "=l"(v2) : "l"(src + 2) : "memory");
                asm volatile("ld.acquire.gpu.b64 %0, [%1];" : "=l"(v3) : "l"(src + 3) : "memory");
                bool ok = ((int)((unsigned)(v0 >> 32) - tgt) >= 0) &
                          ((int)((unsigned)(v1 >> 32) - tgt) >= 0) &
                          ((int)((unsigned)(v2 >> 32) - tgt) >= 0) &
                          ((int)((unsigned)(v3 >> 32) - tgt) >= 0);
                if (ok) break;
            }
            float4 hv;
            hv.x = __uint_as_float((unsigned)v0);
            hv.y = __uint_as_float((unsigned)v1);
            hv.z = __uint_as_float((unsigned)v2);
            hv.w = __uint_as_float((unsigned)v3);
            *(float4*)&hsm[tid * 4] = hv;
        }
        __syncthreads();

        // sumexp bookkeeping for step t-1 (off critical path, overlaps dot)
        if (tid == 0 && t > 0) {
            const float* rp = red + ((t - 1) & 1) * 8;
            float s = 0.f;
#pragma unroll
            for (int q = 0; q < JPB; q++) s += rp[q];
            g_sumexp[(size_t)(t - 1) * NBLK + b] = s;
        }

        // 4 dot products of length 1024 per warp (gate rows i,f,g,o for lane j)
        float a0 = 0.f, a1 = 0.f, a2 = 0.f, a3 = 0.f;
#pragma unroll
        for (int i = 0; i < 8; i++) {
            int k = (lane << 2) + (i << 7);          // conflict-free float4 pattern
            float4 hv = *(const float4*)&hsm[k];
            float4 q;
            q = *(const float4*)&w0[k]; a0 += q.x*hv.x + q.y*hv.y + q.z*hv.z + q.w*hv.w;
            q = *(const float4*)&w1[k]; a1 += q.x*hv.x + q.y*hv.y + q.z*hv.z + q.w*hv.w;
            q = *(const float4*)&w2[k]; a2 += q.x*hv.x + q.y*hv.y + q.z*hv.z + q.w*hv.w;
            q = *(const float4*)&w3[k]; a3 += q.x*hv.x + q.y*hv.y + q.z*hv.z + q.w*hv.w;
        }
#pragma unroll
        for (int off = 16; off > 0; off >>= 1) {
            a0 += __shfl_xor_sync(0xffffffffu, a0, off);
            a1 += __shfl_xor_sync(0xffffffffu, a1, off);
            a2 += __shfl_xor_sync(0xffffffffu, a2, off);
            a3 += __shfl_xor_sync(0xffffffffu, a3, off);
        }

        float gi = 1.0f / (1.0f + expf(-(xi + a0)));
        float gf = 1.0f / (1.0f + expf(-(xf + a1)));
        float gg = tanhf(xg_ + a2);
        float go = 1.0f / (1.0f + expf(-(xo + a3)));
        c_state  = gf * c_state + gi * gg;
        float h  = go * tanhf(c_state);

        // publish {tag,h} immediately — no intra-block sync, no fence needed
        if (lane == 0) {
            unsigned long long pk =
                ((unsigned long long)(base + (unsigned)t + 1u) << 32) |
                (unsigned long long)__float_as_uint(h);
            asm volatile("st.release.gpu.b64 [%0], %1;"
                         :: "l"(&g_hpair[(t + 1) & 1][j]), "l"(pk) : "memory");
            red[(t & 1) * 8 + w] = expf(h);          // h in (-1,1): no max-shift
            if ((int)yt == j) g_hy[t] = h;
        }

        // rotate prefetch registers
        xi = nxi; xf = nxf; xg_ = nxg; xo = nxo; yt = nyt;
    }

    // tail: sumexp for the last step
    __syncthreads();
    if (tid == 0) {
        const float* rp = red + ((T_STEPS - 1) & 1) * 8;
        float s = 0.f;
#pragma unroll
        for (int q = 0; q < JPB; q++) s += rp[q];
        g_sumexp[(size_t)(T_STEPS - 1) * NBLK + b] = s;
    }
}

// ---------------- kernel 3: deterministic loss reduction ----------------
__global__ void __launch_bounds__(256) loss_reduce(float* __restrict__ out)
{
    __shared__ double sred[256];
    double lsum = 0.0;
    for (int t = threadIdx.x; t < T_STEPS; t += 256) {
        float s = 0.0f;
        const float* p = &g_sumexp[(size_t)t * NBLK];
#pragma unroll 8
        for (int b = 0; b < NBLK; b++) s += p[b];
        lsum += (double)(logf(s) - g_hy[t]);
    }
    sred[threadIdx.x] = lsum;
    __syncthreads();
    for (int off = 128; off > 0; off >>= 1) {
        if (threadIdx.x < off) sred[threadIdx.x] += sred[threadIdx.x + off];
        __syncthreads();
    }
    if (threadIdx.x == 0) out[0] = (float)sred[0];
}

// ---------------- launch ----------------
extern "C" void kernel_launch(void* const* d_in, const int* in_sizes, int n_in,
                              void* d_out, int out_size)
{
    const float*     Xs   = (const float*)d_in[0];
    const float*     W_ih = (const float*)d_in[1];
    const float*     W_hh = (const float*)d_in[2];
    const float*     b_ih = (const float*)d_in[3];
    const float*     b_hh = (const float*)d_in[4];
    const long long* ys   = (const long long*)d_in[5];

    cudaFuncSetAttribute(lstm_rnn, cudaFuncAttributeMaxDynamicSharedMemorySize,
                         (int)RNN_SMEM);

    dim3 g1(R_DIM / BN, T_STEPS / BM);
    xg_gemm<<<g1, 256>>>(Xs, W_ih, b_ih, b_hh);
    lstm_rnn<<<NBLK, RTHREADS, RNN_SMEM>>>(W_hh, ys);
    loss_reduce<<<1, 256>>>((float*)d_out);
}

// round 10
// speedup vs baseline: 1.3182x; 1.3182x over previous
#include <cuda_runtime.h>
#include <math.h>

// Problem dims
#define T_STEPS 16384
#define E_DIM   1024
#define H_DIM   1024
#define R_DIM   4096   // 4*H

// Recurrent kernel config
#define NBLK     128   // persistent blocks (one wave, distinct SMs)
#define JPB      8     // h-lanes per block (NBLK*JPB = H_DIM)
#define RTHREADS 256   // 8 warps, 1 warp per h-lane

// GEMM config
#define BM 64
#define BN 64
#define BK 32

// ---------------- device scratch (no allocations allowed) ----------------
__device__ float    g_xg[(size_t)T_STEPS * R_DIM];      // 256 MB input projections
__device__ float    g_hbuf[2][H_DIM];                   // double-buffered hidden state
__device__ float    g_sumexp[(size_t)T_STEPS * NBLK];   // per-(step,block) partial sum(exp(h))
__device__ float    g_hy[T_STEPS];                      // h[y_t] per step
__device__ unsigned g_flag[NBLK][8];                    // per-block step flags, 32B padded

// ---------------- f32x2 helpers (Blackwell packed FFMA) ----------------
__device__ __forceinline__ unsigned long long pk2(float x, float y) {
    unsigned long long r;
    asm("mov.b64 %0, {%1, %2};" : "=l"(r) : "f"(x), "f"(y));
    return r;
}
__device__ __forceinline__ void fma2(unsigned long long& acc,
                                     unsigned long long w, unsigned long long h) {
    asm("fma.rn.f32x2 %0, %1, %2, %0;" : "+l"(acc) : "l"(w), "l"(h));
}
__device__ __forceinline__ float upk_sum(unsigned long long a) {
    float lo, hi;
    asm("mov.b64 {%0, %1}, %2;" : "=f"(lo), "=f"(hi) : "l"(a));
    return lo + hi;
}

// ---------------- kernel 1: xg = Xs @ W_ih^T + b_ih + b_hh ----------------
__global__ void __launch_bounds__(256) xg_gemm(
    const float* __restrict__ Xs, const float* __restrict__ W_ih,
    const float* __restrict__ b_ih, const float* __restrict__ b_hh)
{
    __shared__ float As[BM][BK + 4];
    __shared__ float Bs[BN][BK + 4];

    const int bm  = blockIdx.y * BM;
    const int bn  = blockIdx.x * BN;
    const int tid = threadIdx.x;
    const int tx  = tid & 15;
    const int ty  = tid >> 4;

    float acc[4][4];
#pragma unroll
    for (int i = 0; i < 4; i++)
#pragma unroll
        for (int jj = 0; jj < 4; jj++) acc[i][jj] = 0.0f;

    for (int k0 = 0; k0 < E_DIM; k0 += BK) {
#pragma unroll
        for (int i = 0; i < 2; i++) {
            int idx = tid + i * 256;
            int r   = idx >> 3;
            int c4  = (idx & 7) << 2;
            float4 va = *(const float4*)&Xs[(size_t)(bm + r) * E_DIM + k0 + c4];
            As[r][c4 + 0] = va.x; As[r][c4 + 1] = va.y;
            As[r][c4 + 2] = va.z; As[r][c4 + 3] = va.w;
            float4 vb = *(const float4*)&W_ih[(size_t)(bn + r) * E_DIM + k0 + c4];
            Bs[r][c4 + 0] = vb.x; Bs[r][c4 + 1] = vb.y;
            Bs[r][c4 + 2] = vb.z; Bs[r][c4 + 3] = vb.w;
        }
        __syncthreads();

#pragma unroll
        for (int kk = 0; kk < BK; kk++) {
            float a[4], b[4];
#pragma unroll
            for (int i = 0; i < 4; i++)  a[i]  = As[ty * 4 + i][kk];
#pragma unroll
            for (int jj = 0; jj < 4; jj++) b[jj] = Bs[tx * 4 + jj][kk];
#pragma unroll
            for (int i = 0; i < 4; i++)
#pragma unroll
                for (int jj = 0; jj < 4; jj++)
                    acc[i][jj] += a[i] * b[jj];
        }
        __syncthreads();
    }

#pragma unroll
    for (int i = 0; i < 4; i++) {
        int t = bm + ty * 4 + i;
#pragma unroll
        for (int jj = 0; jj < 4; jj++) {
            int r = bn + tx * 4 + jj;
            g_xg[(size_t)t * R_DIM + r] = acc[i][jj] + __ldg(&b_ih[r]) + __ldg(&b_hh[r]);
        }
    }
}

// ---------------- kernel 2: persistent LSTM recurrence ----------------
// Block b owns h-lanes j = b*8 .. b*8+7 (one warp per lane).
// W_hh slice lives entirely in REGISTERS (128 regs/thread).
// Sync (R3 proven scheme): per-block 4B release flag; 128 threads poll one
// flag each, then fetch that producer's 8 h floats via ldcg.
__global__ void __launch_bounds__(RTHREADS, 1) lstm_rnn(
    const float* __restrict__ W_hh, const long long* __restrict__ ys)
{
    __shared__ float hsm[H_DIM];       // staged h_prev
    __shared__ float red[16];          // parity-buffered per-warp exp partials

    const int tid  = threadIdx.x;
    const int b    = blockIdx.x;
    const int w    = tid >> 5;
    const int lane = tid & 31;
    const int j    = b * JPB + w;

    // ---- load this thread's W slice into registers ----
    // thread (w,lane) holds, for its 4 gate rows, columns k = lane*4 + i*128 + c
    unsigned long long wreg[4][16];
#pragma unroll
    for (int r = 0; r < 4; r++) {
        const float4* src = (const float4*)(W_hh + (size_t)(r * H_DIM + j) * H_DIM);
#pragma unroll
        for (int i = 0; i < 8; i++) {
            float4 v = __ldg(&src[lane + i * 32]);
            wreg[r][2 * i + 0] = pk2(v.x, v.y);
            wreg[r][2 * i + 1] = pk2(v.z, v.w);
        }
    }

    // flag base: only block b writes g_flag[b][0]; uniform at entry across runs
    __shared__ unsigned s_base;
    if (tid == 0) s_base = g_flag[b][0];
    // h_0 = 0
    *(float4*)&hsm[tid * 4] = make_float4(0.f, 0.f, 0.f, 0.f);
    __syncthreads();
    const unsigned base = s_base;

    float c_state = 0.0f;

    // one-step-ahead xg / ys prefetch
    const float* xgp0 = &g_xg[(size_t)0 * R_DIM + j];
    float xi  = __ldg(xgp0 + 0 * H_DIM);
    float xf  = __ldg(xgp0 + 1 * H_DIM);
    float xg_ = __ldg(xgp0 + 2 * H_DIM);
    float xo  = __ldg(xgp0 + 3 * H_DIM);
    long long yt = __ldg(&ys[0]);

    for (int t = 0; t < T_STEPS; t++) {
        // issue next step's xg/ys loads now
        int tn = (t + 1 < T_STEPS) ? t + 1 : t;
        const float* xgp = &g_xg[(size_t)tn * R_DIM + j];
        float nxi = __ldg(xgp + 0 * H_DIM);
        float nxf = __ldg(xgp + 1 * H_DIM);
        float nxg = __ldg(xgp + 2 * H_DIM);
        float nxo = __ldg(xgp + 3 * H_DIM);
        long long nyt = __ldg(&ys[tn]);

        // stage h_prev: thread tid<128 waits on producer block tid, then fetches
        if (t > 0 && tid < NBLK) {
            const unsigned target = base + (unsigned)t;
            unsigned v;
            do {
                asm volatile("ld.acquire.gpu.u32 %0, [%1];"
                             : "=r"(v) : "l"(&g_flag[tid][0]) : "memory");
            } while ((int)(v - target) < 0);
            const float4* src = (const float4*)&g_hbuf[(t - 1) & 1][tid * JPB];
            float4 h0 = __ldcg(src + 0);
            float4 h1 = __ldcg(src + 1);
            *(float4*)&hsm[tid * JPB + 0] = h0;
            *(float4*)&hsm[tid * JPB + 4] = h1;
        }
        __syncthreads();

        // deferred sumexp for step t-1 (off critical path, overlaps dot)
        if (tid == 0 && t > 0) {
            const float* rp = red + ((t - 1) & 1) * 8;
            float s = 0.f;
#pragma unroll
            for (int q = 0; q < JPB; q++) s += rp[q];
            g_sumexp[(size_t)(t - 1) * NBLK + b] = s;
        }

        // 4 dots of length 1024: W in registers, h from smem, packed FFMA2
        unsigned long long acc[4][2];
#pragma unroll
        for (int r = 0; r < 4; r++) { acc[r][0] = 0ull; acc[r][1] = 0ull; }
#pragma unroll
        for (int i = 0; i < 8; i++) {
            float4 hv = *(const float4*)&hsm[(lane << 2) + (i << 7)];
            unsigned long long hlo = pk2(hv.x, hv.y);
            unsigned long long hhi = pk2(hv.z, hv.w);
#pragma unroll
            for (int r = 0; r < 4; r++) {
                fma2(acc[r][0], wreg[r][2 * i + 0], hlo);
                fma2(acc[r][1], wreg[r][2 * i + 1], hhi);
            }
        }
        float a0 = upk_sum(acc[0][0]) + upk_sum(acc[0][1]);
        float a1 = upk_sum(acc[1][0]) + upk_sum(acc[1][1]);
        float a2 = upk_sum(acc[2][0]) + upk_sum(acc[2][1]);
        float a3 = upk_sum(acc[3][0]) + upk_sum(acc[3][1]);
#pragma unroll
        for (int off = 16; off > 0; off >>= 1) {
            a0 += __shfl_xor_sync(0xffffffffu, a0, off);
            a1 += __shfl_xor_sync(0xffffffffu, a1, off);
            a2 += __shfl_xor_sync(0xffffffffu, a2, off);
            a3 += __shfl_xor_sync(0xffffffffu, a3, off);
        }

        float gi = 1.0f / (1.0f + expf(-(xi + a0)));
        float gf = 1.0f / (1.0f + expf(-(xf + a1)));
        float gg = tanhf(xg_ + a2);
        float go = 1.0f / (1.0f + expf(-(xo + a3)));
        c_state  = gf * c_state + gi * gg;
        float h  = go * tanhf(c_state);

        if (lane == 0) {
            g_hbuf[t & 1][j] = h;                    // publish h (weak store)
            red[(t & 1) * 8 + w] = expf(h);          // h in (-1,1): no max-shift
            if ((int)yt == j) g_hy[t] = h;
        }
        __syncthreads();                             // all 8 h stores done
        if (tid == 0) {
            // st.release: A-cumulativity through bar.sync publishes all warps' h
            asm volatile("st.release.gpu.u32 [%0], %1;"
                         :: "l"(&g_flag[b][0]), "r"(base + (unsigned)t + 1u)
                         : "memory");
        }

        xi = nxi; xf = nxf; xg_ = nxg; xo = nxo; yt = nyt;
    }

    // tail: sumexp for the last step
    if (tid == 0) {
        const float* rp = red + ((T_STEPS - 1) & 1) * 8;
        float s = 0.f;
#pragma unroll
        for (int q = 0; q < JPB; q++) s += rp[q];
        g_sumexp[(size_t)(T_STEPS - 1) * NBLK + b] = s;
    }
}

// ---------------- kernel 3: deterministic loss reduction ----------------
__global__ void __launch_bounds__(256) loss_reduce(float* __restrict__ out)
{
    __shared__ double sred[256];
    double lsum = 0.0;
    for (int t = threadIdx.x; t < T_STEPS; t += 256) {
        float s = 0.0f;
        const float* p = &g_sumexp[(size_t)t * NBLK];
#pragma unroll 8
        for (int b = 0; b < NBLK; b++) s += p[b];
        lsum += (double)(logf(s) - g_hy[t]);
    }
    sred[threadIdx.x] = lsum;
    __syncthreads();
    for (int off = 128; off > 0; off >>= 1) {
        if (threadIdx.x < off) sred[threadIdx.x] += sred[threadIdx.x + off];
        __syncthreads();
    }
    if (threadIdx.x == 0) out[0] = (float)sred[0];
}

// ---------------- launch ----------------
extern "C" void kernel_launch(void* const* d_in, const int* in_sizes, int n_in,
                              void* d_out, int out_size)
{
    const float*     Xs   = (const float*)d_in[0];
    const float*     W_ih = (const float*)d_in[1];
    const float*     W_hh = (const float*)d_in[2];
    const float*     b_ih = (const float*)d_in[3];
    const float*     b_hh = (const float*)d_in[4];
    const long long* ys   = (const long long*)d_in[5];

    dim3 g1(R_DIM / BN, T_STEPS / BM);
    xg_gemm<<<g1, 256>>>(Xs, W_ih, b_ih, b_hh);
    lstm_rnn<<<NBLK, RTHREADS>>>(W_hh, ys);
    loss_reduce<<<1, 256>>>((float*)d_out);
}

// round 14
// speedup vs baseline: 1.6882x; 1.2806x over previous
#include <cuda_runtime.h>
#include <math.h>

// Problem dims
#define T_STEPS 16384
#define E_DIM   1024
#define H_DIM   1024
#define R_DIM   4096   // 4*H

// Recurrent kernel config
#define NBLK     128   // persistent blocks (one wave, 1 block/SM by regs)
#define JPB      8     // h-lanes per block (NBLK*JPB = H_DIM)
#define RTHREADS 256   // 8 warps, 1 warp per h-lane

// GEMM config
#define BM 64
#define BN 64
#define BK 32

// ---------------- device scratch (no allocations allowed) ----------------
__device__ float    g_xg[(size_t)T_STEPS * R_DIM];      // 256 MB input projections
__device__ float    g_hbuf[2][H_DIM];                   // double-buffered hidden state
__device__ float    g_sumexp[(size_t)T_STEPS * NBLK];   // per-(step,block) partial sum(exp(h))
__device__ float    g_hy[T_STEPS];                      // h[y_t] per step
__device__ unsigned g_flag[NBLK][8];                    // per-block flag word (32B padded)

// ---------------- f32x2 helpers (Blackwell packed FFMA) ----------------
__device__ __forceinline__ unsigned long long pk2(float x, float y) {
    unsigned long long r;
    asm("mov.b64 %0, {%1, %2};" : "=l"(r) : "f"(x), "f"(y));
    return r;
}
__device__ __forceinline__ void fma2(unsigned long long& acc,
                                     unsigned long long w, unsigned long long h) {
    asm("fma.rn.f32x2 %0, %1, %2, %0;" : "+l"(acc) : "l"(w), "l"(h));
}
__device__ __forceinline__ float upk_sum(unsigned long long a) {
    float lo, hi;
    asm("mov.b64 {%0, %1}, %2;" : "=f"(lo), "=f"(hi) : "l"(a));
    return lo + hi;
}

// ---------------- fast gates: sigma via ex2+rcp, tanh = 2*sigma(2x)-1 ----------------
__device__ __forceinline__ float sigm(float x) {
    float e;
    asm("ex2.approx.ftz.f32 %0, %1;" : "=f"(e) : "f"(x * -1.4426950408889634f));
    float r;
    asm("rcp.approx.ftz.f32 %0, %1;" : "=f"(r) : "f"(1.0f + e));
    return r;
}
__device__ __forceinline__ float tanha(float x) {
    return fmaf(2.0f, sigm(2.0f * x), -1.0f);
}

// ---------------- kernel 1: xg = Xs @ W_ih^T + b_ih + b_hh ----------------
__global__ void __launch_bounds__(256) xg_gemm(
    const float* __restrict__ Xs, const float* __restrict__ W_ih,
    const float* __restrict__ b_ih, const float* __restrict__ b_hh)
{
    __shared__ float As[BM][BK + 4];
    __shared__ float Bs[BN][BK + 4];

    const int bm  = blockIdx.y * BM;
    const int bn  = blockIdx.x * BN;
    const int tid = threadIdx.x;
    const int tx  = tid & 15;
    const int ty  = tid >> 4;

    float acc[4][4];
#pragma unroll
    for (int i = 0; i < 4; i++)
#pragma unroll
        for (int jj = 0; jj < 4; jj++) acc[i][jj] = 0.0f;

    for (int k0 = 0; k0 < E_DIM; k0 += BK) {
#pragma unroll
        for (int i = 0; i < 2; i++) {
            int idx = tid + i * 256;
            int r   = idx >> 3;
            int c4  = (idx & 7) << 2;
            float4 va = *(const float4*)&Xs[(size_t)(bm + r) * E_DIM + k0 + c4];
            As[r][c4 + 0] = va.x; As[r][c4 + 1] = va.y;
            As[r][c4 + 2] = va.z; As[r][c4 + 3] = va.w;
            float4 vb = *(const float4*)&W_ih[(size_t)(bn + r) * E_DIM + k0 + c4];
            Bs[r][c4 + 0] = vb.x; Bs[r][c4 + 1] = vb.y;
            Bs[r][c4 + 2] = vb.z; Bs[r][c4 + 3] = vb.w;
        }
        __syncthreads();

#pragma unroll
        for (int kk = 0; kk < BK; kk++) {
            float a[4], b[4];
#pragma unroll
            for (int i = 0; i < 4; i++)  a[i]  = As[ty * 4 + i][kk];
#pragma unroll
            for (int jj = 0; jj < 4; jj++) b[jj] = Bs[tx * 4 + jj][kk];
#pragma unroll
            for (int i = 0; i < 4; i++)
#pragma unroll
                for (int jj = 0; jj < 4; jj++)
                    acc[i][jj] += a[i] * b[jj];
        }
        __syncthreads();
    }

#pragma unroll
    for (int i = 0; i < 4; i++) {
        int t = bm + ty * 4 + i;
#pragma unroll
        for (int jj = 0; jj < 4; jj++) {
            int r = bn + tx * 4 + jj;
            g_xg[(size_t)t * R_DIM + r] = acc[i][jj] + __ldg(&b_ih[r]) + __ldg(&b_hh[r]);
        }
    }
}

// ---------------- kernel 2: persistent LSTM recurrence ----------------
// Block b owns h-lanes j = b*8 .. b*8+7 (warp w = lane j = b*8+w).
// W_hh slice in registers. Publish: each warp's lane0 does weak STG of its h
// then red.release.gpu.add(+1) on the block flag (target 8 arrivals/step).
// Stagers (tid<128) poll one flag each, fetch 8 h, STS, bump smem chunk
// counter (release). Compute warps gate each 128-elem dot chunk on its
// counter (acquire smem spin) -> dot overlaps data arrival.
__global__ void __launch_bounds__(RTHREADS, 1) lstm_rnn(
    const float* __restrict__ W_hh, const long long* __restrict__ ys)
{
    __shared__ float    hsm[H_DIM];    // staged h_prev
    __shared__ unsigned cnt[8];        // per-chunk ready counters (16 each/step)
    __shared__ float    red[16];       // parity-buffered per-warp exp partials

    const int tid  = threadIdx.x;
    const int b    = blockIdx.x;
    const int w    = tid >> 5;
    const int lane = tid & 31;
    const int j    = b * JPB + w;

    // ---- load this thread's W slice into registers ----
    unsigned long long wreg[4][16];
#pragma unroll
    for (int r = 0; r < 4; r++) {
        const float4* src = (const float4*)(W_hh + (size_t)(r * H_DIM + j) * H_DIM);
#pragma unroll
        for (int i = 0; i < 8; i++) {
            float4 v = __ldg(&src[lane + i * 32]);
            wreg[r][2 * i + 0] = pk2(v.x, v.y);
            wreg[r][2 * i + 1] = pk2(v.z, v.w);
        }
    }

    // flag base (uniform across all blocks at entry; +8*T per completed run)
    __shared__ unsigned s_base;
    if (tid == 0) s_base = g_flag[b][0];
    if (tid < 8)  cnt[tid] = 0u;
    *(float4*)&hsm[tid * 4] = make_float4(0.f, 0.f, 0.f, 0.f);   // h_0 = 0
    __syncthreads();
    const unsigned base = s_base;

    const unsigned cnt_s = (unsigned)__cvta_generic_to_shared(&cnt[0]);
    float c_state = 0.0f;

    // one-step-ahead xg / ys prefetch
    const float* xgp0 = &g_xg[(size_t)0 * R_DIM + j];
    float xi  = __ldg(xgp0 + 0 * H_DIM);
    float xf  = __ldg(xgp0 + 1 * H_DIM);
    float xg_ = __ldg(xgp0 + 2 * H_DIM);
    float xo  = __ldg(xgp0 + 3 * H_DIM);
    long long yt = __ldg(&ys[0]);

    for (int t = 0; t < T_STEPS; t++) {
        // issue next step's xg/ys loads now
        int tn = (t + 1 < T_STEPS) ? t + 1 : t;
        const float* xgp = &g_xg[(size_t)tn * R_DIM + j];
        float nxi = __ldg(xgp + 0 * H_DIM);
        float nxf = __ldg(xgp + 1 * H_DIM);
        float nxg = __ldg(xgp + 2 * H_DIM);
        float nxo = __ldg(xgp + 3 * H_DIM);
        long long nyt = __ldg(&ys[tn]);

        // ---- stage h_prev (tid<128): poll producer flag, fetch, STS, bump cnt
        if (t > 0 && tid < NBLK) {
            const unsigned target = base + 8u * (unsigned)t;
            unsigned v;
            do {
                asm volatile("ld.acquire.gpu.u32 %0, [%1];"
                             : "=r"(v) : "l"(&g_flag[tid][0]) : "memory");
            } while ((int)(v - target) < 0);
            const float4* src = (const float4*)&g_hbuf[(t - 1) & 1][tid * JPB];
            float4 h0 = __ldcg(src + 0);
            float4 h1 = __ldcg(src + 1);
            *(float4*)&hsm[tid * JPB + 0] = h0;
            *(float4*)&hsm[tid * JPB + 4] = h1;
            // chunk (tid>>4) gains one of its 16 stager arrivals
            asm volatile("red.release.cta.shared.add.u32 [%0], %1;"
                         :: "r"(cnt_s + 4u * (unsigned)(tid >> 4)), "r"(1u) : "memory");
        }

        // deferred sumexp for step t-1 (tid0 only; off critical path)
        if (tid == 0 && t > 0) {
            const float* rp = red + ((t - 1) & 1) * 8;
            float s = 0.f;
#pragma unroll
            for (int q = 0; q < JPB; q++) s += rp[q];
            g_sumexp[(size_t)(t - 1) * NBLK + b] = s;
        }

        // ---- chunk-gated dot: 8 chunks of 128, gated on smem counters
        unsigned long long acc[4][2];
#pragma unroll
        for (int r = 0; r < 4; r++) { acc[r][0] = 0ull; acc[r][1] = 0ull; }
        const unsigned ctgt = 16u * (unsigned)t;
#pragma unroll
        for (int i = 0; i < 8; i++) {
            if (t > 0) {
                unsigned cv;
                do {
                    asm volatile("ld.acquire.cta.shared.u32 %0, [%1];"
                                 : "=r"(cv) : "r"(cnt_s + 4u * (unsigned)i) : "memory");
                } while ((int)(cv - ctgt) < 0);
            }
            float4 hv = *(const float4*)&hsm[(lane << 2) + (i << 7)];
            unsigned long long hlo = pk2(hv.x, hv.y);
            unsigned long long hhi = pk2(hv.z, hv.w);
#pragma unroll
            for (int r = 0; r < 4; r++) {
                fma2(acc[r][0], wreg[r][2 * i + 0], hlo);
                fma2(acc[r][1], wreg[r][2 * i + 1], hhi);
            }
        }
        float a0 = upk_sum(acc[0][0]) + upk_sum(acc[0][1]);
        float a1 = upk_sum(acc[1][0]) + upk_sum(acc[1][1]);
        float a2 = upk_sum(acc[2][0]) + upk_sum(acc[2][1]);
        float a3 = upk_sum(acc[3][0]) + upk_sum(acc[3][1]);
#pragma unroll
        for (int off = 16; off > 0; off >>= 1) {
            a0 += __shfl_xor_sync(0xffffffffu, a0, off);
            a1 += __shfl_xor_sync(0xffffffffu, a1, off);
            a2 += __shfl_xor_sync(0xffffffffu, a2, off);
            a3 += __shfl_xor_sync(0xffffffffu, a3, off);
        }

        float gi = sigm(xi + a0);
        float gf = sigm(xf + a1);
        float gg = tanha(xg_ + a2);
        float go = sigm(xo + a3);
        c_state  = gf * c_state + gi * gg;
        float h  = go * tanha(c_state);

        // ---- publish: weak h store + release-RED on block flag (no bar!)
        if (lane == 0) {
            g_hbuf[t & 1][j] = h;
            asm volatile("red.release.gpu.global.add.u32 [%0], %1;"
                         :: "l"(&g_flag[b][0]), "r"(1u) : "memory");
            red[(t & 1) * 8 + w] = __expf(h);        // h in (-1,1): no max-shift
            if ((int)yt == j) g_hy[t] = h;
        }

        __syncthreads();   // sole per-step bar: protects hsm/cnt/red reuse

        xi = nxi; xf = nxf; xg_ = nxg; xo = nxo; yt = nyt;
    }

    // tail: sumexp for the last step
    if (tid == 0) {
        const float* rp = red + ((T_STEPS - 1) & 1) * 8;
        float s = 0.f;
#pragma unroll
        for (int q = 0; q < JPB; q++) s += rp[q];
        g_sumexp[(size_t)(T_STEPS - 1) * NBLK + b] = s;
    }
}

// ---------------- kernel 3: deterministic loss reduction ----------------
__global__ void __launch_bounds__(256) loss_reduce(float* __restrict__ out)
{
    __shared__ double sred[256];
    double lsum = 0.0;
    for (int t = threadIdx.x; t < T_STEPS; t += 256) {
        float s = 0.0f;
        const float* p = &g_sumexp[(size_t)t * NBLK];
#pragma unroll 8
        for (int b = 0; b < NBLK; b++) s += p[b];
        lsum += (double)(logf(s) - g_hy[t]);
    }
    sred[threadIdx.x] = lsum;
    __syncthreads();
    for (int off = 128; off > 0; off >>= 1) {
        if (threadIdx.x < off) sred[threadIdx.x] += sred[threadIdx.x + off];
        __syncthreads();
    }
    if (threadIdx.x == 0) out[0] = (float)sred[0];
}

// ---------------- launch ----------------
extern "C" void kernel_launch(void* const* d_in, const int* in_sizes, int n_in,
                              void* d_out, int out_size)
{
    const float*     Xs   = (const float*)d_in[0];
    const float*     W_ih = (const float*)d_in[1];
    const float*     W_hh = (const float*)d_in[2];
    const float*     b_ih = (const float*)d_in[3];
    const float*     b_hh = (const float*)d_in[4];
    const long long* ys   = (const long long*)d_in[5];

    dim3 g1(R_DIM / BN, T_STEPS / BM);
    xg_gemm<<<g1, 256>>>(Xs, W_ih, b_ih, b_hh);
    lstm_rnn<<<NBLK, RTHREADS>>>(W_hh, ys);
    loss_reduce<<<1, 256>>>((float*)d_out);
}